// round 2
// baseline (speedup 1.0000x reference)
#include <cuda_runtime.h>
#include <math.h>

// ---------------------------------------------------------------------------
// Problem constants
//   B=4, T=8, H=8, D=128, dh=16, N=2048 (q/x0 nodes), M=8192 (edges)
//   Only the edge_attr branch matters (loop overwrites `out`).
// ---------------------------------------------------------------------------
constexpr int QROWS = 32 * 2048;   // 65536  global q rows (b*16384 + h*2048 + a)
constexpr int EROWS = 32 * 8192;   // 262144 global edge rows
constexpr int A_BLOCKS = 1024;     // 256 rows each (32 blocks per (b,h) slab)
constexpr int B_BLOCKS = 256;      // 256 rows each (8 per (b,h) slab)
constexpr int C_BLOCKS = 256;

// Scratch (static device globals — allocation-free per harness rules)
__device__ float g_oproc[(size_t)QROWS * 128];   // 32 MB, q-branch output (qf layout)
__device__ float g_kvpart[A_BLOCKS * 272];       // per-block partial kv(256)+ksum(16)
__device__ float g_kvred[32 * 272];              // reduced per-(b,h)

#define LN1E4_OVER_8 1.1512925464970231f

// ---------------------------------------------------------------------------
// Kernel A: edge branch.
//   For each edge row: kr = Wk1@x+bk1, vr = Wv1@x+bv1 (128 each),
//   rope(kr chunks, time=m>>10), softmax per 16-chunk,
//   accumulate kv[d][e] += k[s][d]*v[s][e], ksum[e] += k[s][e].
// smem (floats): Ws[128][256] | Xs[64][128] (=Vb after GEMM) | Kb[64][128]
//                | bias[256] | ropeC[64] | ropeS[64] | ksred[256]
// ---------------------------------------------------------------------------
__global__ __launch_bounds__(256, 1)
void kernelA(const float* __restrict__ X, const float* __restrict__ Wk,
             const float* __restrict__ bk, const float* __restrict__ Wv,
             const float* __restrict__ bv) {
    extern __shared__ float sm[];
    float* Ws    = sm;                   // 32768
    float* Xs    = sm + 32768;           // 8192 (also V buffer)
    float* Kb    = sm + 40960;           // 8192
    float* sbias = sm + 49152;           // 256
    float* ropeC = sm + 49408;           // 64
    float* ropeS = sm + 49472;           // 64
    float* ksred = sm + 49536;           // 256

    const int t  = threadIdx.x;
    const int tx = t & 31, ty = t >> 5;

    // Load weights transposed into smem: Ws[k][c], c<128 -> Wk, c>=128 -> Wv
    {
        const float* src = (t < 128) ? (Wk + t * 128) : (Wv + (t - 128) * 128);
#pragma unroll
        for (int q = 0; q < 32; q++) {
            float4 w = ((const float4*)src)[q];
            Ws[(4 * q + 0) * 256 + t] = w.x;
            Ws[(4 * q + 1) * 256 + t] = w.y;
            Ws[(4 * q + 2) * 256 + t] = w.z;
            Ws[(4 * q + 3) * 256 + t] = w.w;
        }
        sbias[t] = (t < 128) ? bk[t] : bv[t - 128];
    }
    if (t < 64) {
        int tm = t >> 3, i = t & 7;
        float freq = expf(-(float)i * LN1E4_OVER_8);
        float ang  = (float)tm * freq;
        ropeC[t] = cosf(ang);
        ropeS[t] = sinf(ang);
    }
    __syncthreads();

    float kv_acc = 0.f;               // thread owns kv[d_own][e_own]
    float ks_acc = 0.f;               // slice-partial of ksum[e_own]
    const int d_own = t >> 4, e_own = t & 15;

    const int row_base = blockIdx.x * 256;   // global edge row
    const int m_base   = row_base & 8191;    // node index within slab

    for (int tile = 0; tile < 4; tile++) {
        const int r0 = row_base + tile * 64;

        // Coalesced load of 64x128 input tile
#pragma unroll
        for (int p = 0; p < 8; p++) {
            int idx = t + 256 * p;            // 2048 float4s
            int rr = idx >> 5, qq = idx & 31;
            ((float4*)Xs)[rr * 32 + qq] =
                ((const float4*)(X + (size_t)(r0 + rr) * 128))[qq];
        }
        __syncthreads();

        // GEMM: 64 rows x 256 cols, K=128. Micro-tile 8x8 per thread.
        float acc[8][8];
#pragma unroll
        for (int i = 0; i < 8; i++)
#pragma unroll
            for (int j = 0; j < 8; j++) acc[i][j] = 0.f;

#pragma unroll 4
        for (int k4 = 0; k4 < 128; k4 += 4) {
            float4 xv[8];
#pragma unroll
            for (int ri = 0; ri < 8; ri++)
                xv[ri] = *(const float4*)(Xs + (ty * 8 + ri) * 128 + k4);
            float wv[4][8];
#pragma unroll
            for (int kk = 0; kk < 4; kk++)
#pragma unroll
                for (int j = 0; j < 8; j++)
                    wv[kk][j] = Ws[(k4 + kk) * 256 + tx + 32 * j];
#pragma unroll
            for (int ri = 0; ri < 8; ri++) {
                float4 x = xv[ri];
#pragma unroll
                for (int j = 0; j < 8; j++) {
                    acc[ri][j] += x.x * wv[0][j];
                    acc[ri][j] += x.y * wv[1][j];
                    acc[ri][j] += x.z * wv[2][j];
                    acc[ri][j] += x.w * wv[3][j];
                }
            }
        }
        __syncthreads();   // Xs reads done; safe to overwrite as V buffer

        // Store K (Kb) and V (Xs) with bias
#pragma unroll
        for (int ri = 0; ri < 8; ri++) {
            int rr = ty * 8 + ri;
#pragma unroll
            for (int j = 0; j < 8; j++) {
                int c = tx + 32 * j;
                float val = acc[ri][j] + sbias[c];
                if (j < 4) Kb[rr * 128 + c] = val;
                else       Xs[rr * 128 + (c - 128)] = val;
            }
        }
        __syncthreads();

        // rope + softmax on K, per (row, subrow) unit
#pragma unroll
        for (int uu = 0; uu < 2; uu++) {
            int u  = t + 256 * uu;
            int rr = u >> 3, r = u & 7;
            int m  = m_base + tile * 64 + rr;
            int tmo = (m >> 10) << 3;          // rope table row
            float* kp = Kb + rr * 128 + r * 16;
            float kx[16];
#pragma unroll
            for (int q = 0; q < 4; q++) {
                float4 v = *(float4*)(kp + 4 * q);
                kx[4*q] = v.x; kx[4*q+1] = v.y; kx[4*q+2] = v.z; kx[4*q+3] = v.w;
            }
#pragma unroll
            for (int i = 0; i < 8; i++) {
                float c = ropeC[tmo + i], s = ropeS[tmo + i];
                float a0 = kx[2*i], a1 = kx[2*i+1];
                kx[2*i]   = a0 * c - a1 * s;
                kx[2*i+1] = a0 * s + a1 * c;
            }
            float mx = kx[0];
#pragma unroll
            for (int i = 1; i < 16; i++) mx = fmaxf(mx, kx[i]);
            float ssum = 0.f;
#pragma unroll
            for (int i = 0; i < 16; i++) { kx[i] = __expf(kx[i] - mx); ssum += kx[i]; }
            float inv = 1.0f / ssum;
#pragma unroll
            for (int i = 0; i < 16; i++) kx[i] *= inv;
#pragma unroll
            for (int q = 0; q < 4; q++)
                *(float4*)(kp + 4 * q) =
                    make_float4(kx[4*q], kx[4*q+1], kx[4*q+2], kx[4*q+3]);
        }
        __syncthreads();

        // kv accumulation: each thread owns one kv entry (broadcast-friendly)
#pragma unroll 8
        for (int u = 0; u < 512; u++) {
            int base = (u >> 3) * 128 + (u & 7) * 16;
            kv_acc += Kb[base + d_own] * Xs[base + e_own];
        }
        // ksum: thread sums its 32-unit slice for dim e_own
#pragma unroll 8
        for (int u2 = 0; u2 < 32; u2++) {
            int u = d_own * 32 + u2;
            int base = (u >> 3) * 128 + (u & 7) * 16;
            ks_acc += Kb[base + e_own];
        }
        __syncthreads();
    }

    g_kvpart[blockIdx.x * 272 + t] = kv_acc;
    ksred[t] = ks_acc;
    __syncthreads();
    if (t < 16) {
        float s = 0.f;
#pragma unroll
        for (int j = 0; j < 16; j++) s += ksred[j * 16 + t];
        g_kvpart[blockIdx.x * 272 + 256 + t] = s;
    }
}

// ---------------------------------------------------------------------------
// Reduce block partials -> per-(b,h) kv + ksum. 32 groups x 32 blocks each.
// ---------------------------------------------------------------------------
__global__ void kernelR() {
    int g = blockIdx.x, v = threadIdx.x;   // 272 threads
    float s = 0.f;
#pragma unroll 8
    for (int p = 0; p < 32; p++) s += g_kvpart[(g * 32 + p) * 272 + v];
    g_kvred[g * 272 + v] = s;
}

// ---------------------------------------------------------------------------
// Kernel B: q branch. qr = Wq@x+bq, softmax per 16-chunk, rope(time=a>>8),
//   Dinv = 1/max(q.ksum,1e-8), o = q + (q@kv)*Dinv  -> g_oproc (qf layout).
// smem: Ws[128][128] | Xs[64][128] (=Q buffer) | bias[128] | rope 128 | skv 272
// ---------------------------------------------------------------------------
__global__ __launch_bounds__(256, 1)
void kernelB(const float* __restrict__ Q, const float* __restrict__ Wq,
             const float* __restrict__ bq) {
    extern __shared__ float sm[];
    float* Ws    = sm;             // 16384
    float* Xs    = sm + 16384;     // 8192
    float* sbias = sm + 24576;     // 128
    float* ropeC = sm + 24704;     // 64
    float* ropeS = sm + 24768;     // 64
    float* skv   = sm + 24832;     // 272

    const int t = threadIdx.x;
    const int tx = t & 31, ty = t >> 5;

    if (t < 128) {
        const float* src = Wq + t * 128;
#pragma unroll
        for (int q = 0; q < 32; q++) {
            float4 w = ((const float4*)src)[q];
            Ws[(4*q+0)*128 + t] = w.x; Ws[(4*q+1)*128 + t] = w.y;
            Ws[(4*q+2)*128 + t] = w.z; Ws[(4*q+3)*128 + t] = w.w;
        }
        sbias[t] = bq[t];
    }
    {
        int g = blockIdx.x >> 3;   // (b,h) group: 8 blocks per 2048-row slab
        for (int i = t; i < 272; i += 256) skv[i] = g_kvred[g * 272 + i];
    }
    if (t < 64) {
        int tm = t >> 3, i = t & 7;
        float freq = expf(-(float)i * LN1E4_OVER_8);
        float ang  = (float)tm * freq;
        ropeC[t] = cosf(ang);
        ropeS[t] = sinf(ang);
    }
    __syncthreads();

    const int row_base = blockIdx.x * 256;
    const int a_base   = row_base & 2047;

    for (int tile = 0; tile < 4; tile++) {
        const int r0 = row_base + tile * 64;
#pragma unroll
        for (int p = 0; p < 8; p++) {
            int idx = t + 256 * p;
            int rr = idx >> 5, qq = idx & 31;
            ((float4*)Xs)[rr * 32 + qq] =
                ((const float4*)(Q + (size_t)(r0 + rr) * 128))[qq];
        }
        __syncthreads();

        float acc[8][4];
#pragma unroll
        for (int i = 0; i < 8; i++)
#pragma unroll
            for (int j = 0; j < 4; j++) acc[i][j] = 0.f;

#pragma unroll 4
        for (int k4 = 0; k4 < 128; k4 += 4) {
            float4 xv[8];
#pragma unroll
            for (int ri = 0; ri < 8; ri++)
                xv[ri] = *(const float4*)(Xs + (ty * 8 + ri) * 128 + k4);
            float wv[4][4];
#pragma unroll
            for (int kk = 0; kk < 4; kk++)
#pragma unroll
                for (int j = 0; j < 4; j++)
                    wv[kk][j] = Ws[(k4 + kk) * 128 + tx + 32 * j];
#pragma unroll
            for (int ri = 0; ri < 8; ri++) {
                float4 x = xv[ri];
#pragma unroll
                for (int j = 0; j < 4; j++) {
                    acc[ri][j] += x.x * wv[0][j];
                    acc[ri][j] += x.y * wv[1][j];
                    acc[ri][j] += x.z * wv[2][j];
                    acc[ri][j] += x.w * wv[3][j];
                }
            }
        }
        __syncthreads();

        // store projected q (+bias) back into Xs
#pragma unroll
        for (int ri = 0; ri < 8; ri++) {
            int rr = ty * 8 + ri;
#pragma unroll
            for (int j = 0; j < 4; j++) {
                int c = tx + 32 * j;
                Xs[rr * 128 + c] = acc[ri][j] + sbias[c];
            }
        }
        __syncthreads();

        // epilogue per (row, subrow)
#pragma unroll
        for (int uu = 0; uu < 2; uu++) {
            int u  = t + 256 * uu;
            int rr = u >> 3, r = u & 7;
            int a  = a_base + tile * 64 + rr;
            int tmo = (a >> 8) << 3;
            float* qp = Xs + rr * 128 + r * 16;
            float qx[16];
#pragma unroll
            for (int q = 0; q < 4; q++) {
                float4 v = *(float4*)(qp + 4 * q);
                qx[4*q] = v.x; qx[4*q+1] = v.y; qx[4*q+2] = v.z; qx[4*q+3] = v.w;
            }
            // softmax FIRST (reference order for q)
            float mx = qx[0];
#pragma unroll
            for (int i = 1; i < 16; i++) mx = fmaxf(mx, qx[i]);
            float ssum = 0.f;
#pragma unroll
            for (int i = 0; i < 16; i++) { qx[i] = __expf(qx[i] - mx); ssum += qx[i]; }
            float inv = 1.0f / ssum;
#pragma unroll
            for (int i = 0; i < 16; i++) qx[i] *= inv;
            // then rope
#pragma unroll
            for (int i = 0; i < 8; i++) {
                float c = ropeC[tmo + i], s = ropeS[tmo + i];
                float a0 = qx[2*i], a1 = qx[2*i+1];
                qx[2*i]   = a0 * c - a1 * s;
                qx[2*i+1] = a0 * s + a1 * c;
            }
            // D_inv and o = q + (q@kv)*Dinv
            float dotv = 0.f;
#pragma unroll
            for (int e = 0; e < 16; e++) dotv += qx[e] * skv[256 + e];
            float Dinv = 1.0f / fmaxf(dotv, 1e-8f);
            float o[16];
#pragma unroll
            for (int e = 0; e < 16; e++) {
                float s = 0.f;
#pragma unroll
                for (int d = 0; d < 16; d++) s += qx[d] * skv[d * 16 + e];
                o[e] = qx[e] + s * Dinv;
            }
            float* op = g_oproc + (size_t)(r0 + rr) * 128 + r * 16;
#pragma unroll
            for (int q = 0; q < 4; q++)
                *(float4*)(op + 4 * q) =
                    make_float4(o[4*q], o[4*q+1], o[4*q+2], o[4*q+3]);
        }
        __syncthreads();
    }
}

// ---------------------------------------------------------------------------
// Kernel C: gather heads -> combined row, GEMM with Wo, +bo, write d_out.
//   combined[b][s][16h+e] = oproc[b*16384 + h*2048 + s/8][16*(s%8)+e]
// ---------------------------------------------------------------------------
__global__ __launch_bounds__(256, 1)
void kernelC(const float* __restrict__ Wo, const float* __restrict__ bo,
             float* __restrict__ out) {
    extern __shared__ float sm[];
    float* Ws    = sm;             // 16384
    float* Xs    = sm + 16384;     // 8192
    float* sbias = sm + 24576;     // 128

    const int t = threadIdx.x;
    const int tx = t & 31, ty = t >> 5;

    if (t < 128) {
        const float* src = Wo + t * 128;
#pragma unroll
        for (int q = 0; q < 32; q++) {
            float4 w = ((const float4*)src)[q];
            Ws[(4*q+0)*128 + t] = w.x; Ws[(4*q+1)*128 + t] = w.y;
            Ws[(4*q+2)*128 + t] = w.z; Ws[(4*q+3)*128 + t] = w.w;
        }
        sbias[t] = bo[t];
    }
    __syncthreads();

    const int row_base = blockIdx.x * 256;   // global s-row

    for (int tile = 0; tile < 4; tile++) {
        const int r0 = row_base + tile * 64;
        const int b  = r0 >> 14;
        // gather combined tile
#pragma unroll
        for (int p = 0; p < 8; p++) {
            int idx = t + 256 * p;
            int rr = idx >> 5, qq = idx & 31;
            int gs = r0 + rr;
            int s  = gs & 16383;
            int a  = s >> 3, r = s & 7;
            int h  = qq >> 2, e0 = (qq & 3) * 4;
            const float4* src = (const float4*)(g_oproc +
                ((size_t)b * 16384 + h * 2048 + a) * 128 + r * 16 + e0);
            ((float4*)Xs)[rr * 32 + qq] = *src;
        }
        __syncthreads();

        float acc[8][4];
#pragma unroll
        for (int i = 0; i < 8; i++)
#pragma unroll
            for (int j = 0; j < 4; j++) acc[i][j] = 0.f;

#pragma unroll 4
        for (int k4 = 0; k4 < 128; k4 += 4) {
            float4 xv[8];
#pragma unroll
            for (int ri = 0; ri < 8; ri++)
                xv[ri] = *(const float4*)(Xs + (ty * 8 + ri) * 128 + k4);
            float wv[4][4];
#pragma unroll
            for (int kk = 0; kk < 4; kk++)
#pragma unroll
                for (int j = 0; j < 4; j++)
                    wv[kk][j] = Ws[(k4 + kk) * 128 + tx + 32 * j];
#pragma unroll
            for (int ri = 0; ri < 8; ri++) {
                float4 x = xv[ri];
#pragma unroll
                for (int j = 0; j < 4; j++) {
                    acc[ri][j] += x.x * wv[0][j];
                    acc[ri][j] += x.y * wv[1][j];
                    acc[ri][j] += x.z * wv[2][j];
                    acc[ri][j] += x.w * wv[3][j];
                }
            }
        }
        __syncthreads();

#pragma unroll
        for (int ri = 0; ri < 8; ri++) {
            int gs = r0 + ty * 8 + ri;
#pragma unroll
            for (int j = 0; j < 4; j++) {
                int c = tx + 32 * j;
                out[(size_t)gs * 128 + c] = acc[ri][j] + sbias[c];
            }
        }
    }
}

// ---------------------------------------------------------------------------
// Inputs (metadata order): 0 x_0, 1 edge_attr, 2 q_data, 3 Wq, 4 bq,
//   5 Wk0, 6 bk0, 7 Wv0, 8 bv0, 9 Wk1, 10 bk1, 11 Wv1, 12 bv1, 13 Wo, 14 bo
// x_0 / Wk0 / Wv0 branch is dead (loop overwrites `out`) -> skipped.
// ---------------------------------------------------------------------------
extern "C" void kernel_launch(void* const* d_in, const int* in_sizes, int n_in,
                              void* d_out, int out_size) {
    const float* edge = (const float*)d_in[1];
    const float* qdat = (const float*)d_in[2];
    const float* Wq   = (const float*)d_in[3];
    const float* bq   = (const float*)d_in[4];
    const float* Wk1  = (const float*)d_in[9];
    const float* bk1  = (const float*)d_in[10];
    const float* Wv1  = (const float*)d_in[11];
    const float* bv1  = (const float*)d_in[12];
    const float* Wo   = (const float*)d_in[13];
    const float* bo   = (const float*)d_in[14];
    float* out = (float*)d_out;

    const size_t smA = (size_t)(32768 + 8192 + 8192 + 256 + 64 + 64 + 256) * 4;
    const size_t smB = (size_t)(16384 + 8192 + 128 + 64 + 64 + 272) * 4;
    const size_t smC = (size_t)(16384 + 8192 + 128) * 4;

    cudaFuncSetAttribute(kernelA, cudaFuncAttributeMaxDynamicSharedMemorySize, (int)smA);
    cudaFuncSetAttribute(kernelB, cudaFuncAttributeMaxDynamicSharedMemorySize, (int)smB);
    cudaFuncSetAttribute(kernelC, cudaFuncAttributeMaxDynamicSharedMemorySize, (int)smC);

    kernelA<<<A_BLOCKS, 256, smA>>>(edge, Wk1, bk1, Wv1, bv1);
    kernelR<<<32, 272>>>();
    kernelB<<<B_BLOCKS, 256, smB>>>(qdat, Wq, bq);
    kernelC<<<C_BLOCKS, 256, smC>>>(Wo, bo, out);
}